// round 1
// baseline (speedup 1.0000x reference)
#include <cuda_runtime.h>
#include <math.h>

#define U_N 100000
#define I_N 50000
#define E_N 2000000
#define D_N 128
#define B_N 4096

// ---------------- device scratch (static, allocation-free) ----------------
__device__ float g_hu[2][(size_t)U_N * D_N];   // 2 x 51.2 MB
__device__ float g_hi[2][(size_t)I_N * D_N];   // 2 x 25.6 MB
__device__ float g_norm[E_N];                  // 8 MB
__device__ int   g_deg_u[U_N];
__device__ int   g_deg_i[I_N];
__device__ float g_acc_u[(size_t)B_N * D_N];   // gathered user embeddings (2 MB)
__device__ float g_acc_i[(size_t)B_N * D_N];   // gathered item embeddings (2 MB)

// ---------------- kernels ----------------

__global__ void zero_deg_kernel() {
    int t = blockIdx.x * blockDim.x + threadIdx.x;
    if (t < U_N) g_deg_u[t] = 0;
    if (t < I_N) g_deg_i[t] = 0;
}

__global__ void degree_kernel(const int* __restrict__ u_idx,
                              const int* __restrict__ i_idx) {
    int e = blockIdx.x * blockDim.x + threadIdx.x;
    if (e >= E_N) return;
    atomicAdd(&g_deg_u[u_idx[e]], 1);
    atomicAdd(&g_deg_i[i_idx[e]], 1);
}

__global__ void norm_kernel(const int* __restrict__ u_idx,
                            const int* __restrict__ i_idx) {
    int e = blockIdx.x * blockDim.x + threadIdx.x;
    if (e >= E_N) return;
    float du = (float)g_deg_u[u_idx[e]];
    float di = (float)g_deg_i[i_idx[e]];
    g_norm[e] = rsqrtf(du * di);
}

// copy user_feat -> g_hu[0], item_feat -> g_hi[0] (float4 vectorized)
__global__ void init_feat_kernel(const float4* __restrict__ user_feat,
                                 const float4* __restrict__ item_feat,
                                 float4* __restrict__ hu0,
                                 float4* __restrict__ hi0) {
    int t = blockIdx.x * blockDim.x + threadIdx.x;
    const int nu = U_N * D_N / 4;
    const int ni = I_N * D_N / 4;
    if (t < nu) {
        hu0[t] = user_feat[t];
    } else if (t < nu + ni) {
        hi0[t - nu] = item_feat[t - nu];
    }
}

// generic double-buffer copy: dst_hu <- src_hu, dst_hi <- src_hi
__global__ void copy_buf_kernel(const float4* __restrict__ src_hu,
                                const float4* __restrict__ src_hi,
                                float4* __restrict__ dst_hu,
                                float4* __restrict__ dst_hi) {
    int t = blockIdx.x * blockDim.x + threadIdx.x;
    const int nu = U_N * D_N / 4;
    const int ni = I_N * D_N / 4;
    if (t < nu) {
        dst_hu[t] = src_hu[t];
    } else if (t < nu + ni) {
        dst_hi[t - nu] = src_hi[t - nu];
    }
}

// acc_u[b] = user_feat[ui[b]], acc_i[b] = item_feat[ii[b]]; also zero loss slot
__global__ void acc_init_kernel(const float4* __restrict__ user_feat,
                                const float4* __restrict__ item_feat,
                                const int* __restrict__ ui,
                                const int* __restrict__ ii,
                                float* __restrict__ loss_out,
                                int has_loss) {
    int t = blockIdx.x * blockDim.x + threadIdx.x;  // over B*D/4
    const int per_row = D_N / 4;
    if (t >= B_N * per_row) return;
    int b = t / per_row;
    int d = t - b * per_row;
    ((float4*)g_acc_u)[t] = user_feat[(size_t)ui[b] * per_row + d];
    ((float4*)g_acc_i)[t] = item_feat[(size_t)ii[b] * per_row + d];
    if (t == 0 && has_loss) *loss_out = 0.0f;
}

// Fused bipartite scatter: warp w in [0,E) does hi_src[i] -> hu_dst[u],
// warp w in [E,2E) does hu_src[u] -> hi_dst[i]. One warp per edge,
// lane handles one float4 of the 128-dim row. Vectorized red.global.
__global__ void edge_kernel(const int* __restrict__ u_idx,
                            const int* __restrict__ i_idx,
                            const float* __restrict__ hu_src,
                            const float* __restrict__ hi_src,
                            float* __restrict__ hu_dst,
                            float* __restrict__ hi_dst) {
    long long w = ((long long)blockIdx.x * blockDim.x + threadIdx.x) >> 5;
    int lane = threadIdx.x & 31;
    if (w >= 2LL * E_N) return;

    int e;
    const float* src;
    float* dst;
    if (w < E_N) {
        e = (int)w;
        src = hi_src + (size_t)i_idx[e] * D_N;
        dst = hu_dst + (size_t)u_idx[e] * D_N;
    } else {
        e = (int)(w - E_N);
        src = hu_src + (size_t)u_idx[e] * D_N;
        dst = hi_dst + (size_t)i_idx[e] * D_N;
    }
    float n = g_norm[e];
    float4 v = *(const float4*)(src + lane * 4);
    v.x *= n; v.y *= n; v.z *= n; v.w *= n;
    asm volatile("red.global.add.v4.f32 [%0], {%1,%2,%3,%4};"
                 :: "l"(dst + lane * 4),
                    "f"(v.x), "f"(v.y), "f"(v.z), "f"(v.w)
                 : "memory");
}

// acc_u[b] += c * hu_new[ui[b]] ; acc_i[b] += c * hi_new[ii[b]]
__global__ void acc_gather_kernel(const float4* __restrict__ hu_new,
                                  const float4* __restrict__ hi_new,
                                  const int* __restrict__ ui,
                                  const int* __restrict__ ii,
                                  float coef) {
    int t = blockIdx.x * blockDim.x + threadIdx.x;
    const int per_row = D_N / 4;
    if (t >= B_N * per_row) return;
    int b = t / per_row;
    int d = t - b * per_row;

    float4 a = ((float4*)g_acc_u)[t];
    float4 h = hu_new[(size_t)ui[b] * per_row + d];
    a.x += coef * h.x; a.y += coef * h.y; a.z += coef * h.z; a.w += coef * h.w;
    ((float4*)g_acc_u)[t] = a;

    float4 ai = ((float4*)g_acc_i)[t];
    float4 hiv = hi_new[(size_t)ii[b] * per_row + d];
    ai.x += coef * hiv.x; ai.y += coef * hiv.y; ai.z += coef * hiv.z; ai.w += coef * hiv.w;
    ((float4*)g_acc_i)[t] = ai;
}

// one warp per b: dot(acc_u[b], acc_i[b]) -> sigmoid -> pred; BCE term -> loss
__global__ void score_kernel(const float* __restrict__ labels,
                             float* __restrict__ pred_out,
                             float* __restrict__ loss_out,
                             int has_loss) {
    int warp = (blockIdx.x * blockDim.x + threadIdx.x) >> 5;
    int lane = threadIdx.x & 31;
    if (warp >= B_N) return;

    const float4* au = (const float4*)(g_acc_u + (size_t)warp * D_N);
    const float4* ai = (const float4*)(g_acc_i + (size_t)warp * D_N);
    float4 a = au[lane];
    float4 b = ai[lane];
    float s = a.x * b.x + a.y * b.y + a.z * b.z + a.w * b.w;
    #pragma unroll
    for (int off = 16; off > 0; off >>= 1)
        s += __shfl_down_sync(0xFFFFFFFFu, s, off);

    if (lane == 0) {
        float z = 1.0f / (1.0f + expf(-s));   // sigmoid(score)
        pred_out[warp] = z;
        if (has_loss) {
            float lbl = labels[warp];
            float term = fmaxf(z, 0.0f) - z * lbl + log1pf(expf(-fabsf(z)));
            atomicAdd(loss_out, term * (1.0f / (float)B_N));
        }
    }
}

// ---------------- host launch ----------------
extern "C" void kernel_launch(void* const* d_in, const int* in_sizes, int n_in,
                              void* d_out, int out_size) {
    const float* user_feat = (const float*)d_in[0];
    const float* item_feat = (const float*)d_in[1];
    const int*   u_idx     = (const int*)d_in[2];
    const int*   i_idx     = (const int*)d_in[3];
    const int*   ui        = (const int*)d_in[4];
    const int*   ii        = (const int*)d_in[5];
    const float* labels    = (const float*)d_in[6];

    float* out = (float*)d_out;
    int has_loss = (out_size > B_N) ? 1 : 0;
    float* pred_out = out + (out_size - B_N);
    float* loss_out = out;  // only written when has_loss

    float* hu_base; float* hi_base;
    cudaGetSymbolAddress((void**)&hu_base, g_hu);
    cudaGetSymbolAddress((void**)&hi_base, g_hi);
    float* hu[2] = { hu_base, hu_base + (size_t)U_N * D_N };
    float* hi[2] = { hi_base, hi_base + (size_t)I_N * D_N };

    const int T = 256;
    const int nu4 = U_N * D_N / 4;
    const int ni4 = I_N * D_N / 4;
    const int feat_blocks = (nu4 + ni4 + T - 1) / T;
    const int acc_blocks  = (B_N * (D_N / 4) + T - 1) / T;

    // 1) degrees + per-edge norms
    zero_deg_kernel<<<(U_N + T - 1) / T, T>>>();
    degree_kernel<<<(E_N + T - 1) / T, T>>>(u_idx, i_idx);
    norm_kernel<<<(E_N + T - 1) / T, T>>>(u_idx, i_idx);

    // 2) init feature buffers + scoring accumulators
    init_feat_kernel<<<feat_blocks, T>>>((const float4*)user_feat,
                                         (const float4*)item_feat,
                                         (float4*)hu[0], (float4*)hi[0]);
    acc_init_kernel<<<acc_blocks, T>>>((const float4*)user_feat,
                                       (const float4*)item_feat,
                                       ui, ii, loss_out, has_loss);

    // 3) three propagation layers (ping-pong buffers)
    const long long edge_warps = 2LL * E_N;
    const int edge_blocks = (int)((edge_warps * 32 + T - 1) / T);
    int cur = 0;
    const float coefs[3] = { 1.0f / 2.0f, 1.0f / 3.0f, 1.0f / 4.0f };
    for (int l = 0; l < 3; l++) {
        int nxt = 1 - cur;
        copy_buf_kernel<<<feat_blocks, T>>>((const float4*)hu[cur],
                                            (const float4*)hi[cur],
                                            (float4*)hu[nxt], (float4*)hi[nxt]);
        edge_kernel<<<edge_blocks, T>>>(u_idx, i_idx,
                                        hu[cur], hi[cur],
                                        hu[nxt], hi[nxt]);
        acc_gather_kernel<<<acc_blocks, T>>>((const float4*)hu[nxt],
                                             (const float4*)hi[nxt],
                                             ui, ii, coefs[l]);
        cur = nxt;
    }

    // 4) scoring + loss
    score_kernel<<<(B_N * 32 + T - 1) / T, T>>>(labels, pred_out, loss_out, has_loss);
}

// round 2
// speedup vs baseline: 2.6149x; 2.6149x over previous
#include <cuda_runtime.h>
#include <math.h>

#define U_N 100000
#define I_N 50000
#define E_N 2000000
#define D_N 128
#define B_N 4096

// ---------------- device scratch (static, allocation-free) ----------------
__device__ float g_hu[2][(size_t)U_N * D_N];   // 2 x 51.2 MB
__device__ float g_hi[2][(size_t)I_N * D_N];   // 2 x 25.6 MB
__device__ int   g_deg_u[U_N];
__device__ int   g_deg_i[I_N];
__device__ int   g_row_u[U_N + 1];
__device__ int   g_row_i[I_N + 1];
__device__ int   g_cur_u[U_N];
__device__ int   g_cur_i[I_N];
__device__ int   g_col_u[E_N];                 // CSR by user: item neighbor ids
__device__ float g_nrm_u[E_N];
__device__ int   g_col_i[E_N];                 // CSR by item: user neighbor ids
__device__ float g_nrm_i[E_N];
__device__ float g_acc_u[(size_t)B_N * D_N];   // gathered user embeddings (2 MB)
__device__ float g_acc_i[(size_t)B_N * D_N];   // gathered item embeddings (2 MB)

// ---------------- CSR construction ----------------

__global__ void zero_deg_kernel() {
    int t = blockIdx.x * blockDim.x + threadIdx.x;
    if (t < U_N) g_deg_u[t] = 0;
    if (t < I_N) g_deg_i[t] = 0;
}

__global__ void degree_kernel(const int* __restrict__ u_idx,
                              const int* __restrict__ i_idx) {
    int e = blockIdx.x * blockDim.x + threadIdx.x;
    if (e >= E_N) return;
    atomicAdd(&g_deg_u[u_idx[e]], 1);
    atomicAdd(&g_deg_i[i_idx[e]], 1);
}

// Single-block sequential-chunk Hillis-Steele exclusive scan.
// Launched with gridDim=2: block 0 scans deg_u -> row_u, block 1 deg_i -> row_i.
__global__ void scan2_kernel() {
    const int* deg = (blockIdx.x == 0) ? g_deg_u : g_deg_i;
    int* row_ptr   = (blockIdx.x == 0) ? g_row_u : g_row_i;
    const int n    = (blockIdx.x == 0) ? U_N : I_N;

    __shared__ int buf[1024];
    __shared__ int carry;
    int tid = threadIdx.x;
    if (tid == 0) carry = 0;
    __syncthreads();

    for (int base = 0; base < n; base += 1024) {
        int idx = base + tid;
        int v = (idx < n) ? deg[idx] : 0;
        buf[tid] = v;
        __syncthreads();
        #pragma unroll
        for (int off = 1; off < 1024; off <<= 1) {
            int t = (tid >= off) ? buf[tid - off] : 0;
            __syncthreads();
            buf[tid] += t;
            __syncthreads();
        }
        if (idx < n) row_ptr[idx] = carry + buf[tid] - v;  // exclusive
        int blocktotal = buf[1023];
        __syncthreads();
        if (tid == 0) carry += blocktotal;
        __syncthreads();
    }
    if (tid == 0) row_ptr[n] = carry;
}

__global__ void cursor_init_kernel() {
    int t = blockIdx.x * blockDim.x + threadIdx.x;
    if (t < U_N) g_cur_u[t] = g_row_u[t];
    if (t < I_N) g_cur_i[t] = g_row_i[t];
}

// Scatter each edge into both CSR structures, computing the symmetric norm.
__global__ void fill_kernel(const int* __restrict__ u_idx,
                            const int* __restrict__ i_idx) {
    int e = blockIdx.x * blockDim.x + threadIdx.x;
    if (e >= E_N) return;
    int u = u_idx[e];
    int i = i_idx[e];
    float n = rsqrtf((float)g_deg_u[u] * (float)g_deg_i[i]);
    int pu = atomicAdd(&g_cur_u[u], 1);
    g_col_u[pu] = i;
    g_nrm_u[pu] = n;
    int pi = atomicAdd(&g_cur_i[i], 1);
    g_col_i[pi] = u;
    g_nrm_i[pi] = n;
}

// ---------------- propagation (pure gather, no float atomics) ----------------
// One warp per destination row; lane owns one float4 column chunk.
// new_dst[d] = self[d] + sum_k nrm[k] * src[col[k]]
__global__ void gather_kernel(const float4* __restrict__ src_u,
                              const float4* __restrict__ src_i,
                              float4* __restrict__ dst_u,
                              float4* __restrict__ dst_i) {
    int w = (blockIdx.x * blockDim.x + threadIdx.x) >> 5;
    int lane = threadIdx.x & 31;

    const int* rp; const int* col; const float* nrm;
    const float4* src; const float4* self; float4* dst; int d;
    if (w < U_N) {
        d = w;
        rp = g_row_u; col = g_col_u; nrm = g_nrm_u;
        src = src_i; self = src_u; dst = dst_u;
    } else if (w < U_N + I_N) {
        d = w - U_N;
        rp = g_row_i; col = g_col_i; nrm = g_nrm_i;
        src = src_u; self = src_i; dst = dst_i;
    } else {
        return;
    }

    int start = rp[d];
    int end   = rp[d + 1];
    float4 acc = self[(size_t)d * 32 + lane];

    int k = start;
    for (; k + 4 <= end; k += 4) {
        int   s0 = col[k],     s1 = col[k + 1], s2 = col[k + 2], s3 = col[k + 3];
        float n0 = nrm[k],     n1 = nrm[k + 1], n2 = nrm[k + 2], n3 = nrm[k + 3];
        float4 v0 = src[(size_t)s0 * 32 + lane];
        float4 v1 = src[(size_t)s1 * 32 + lane];
        float4 v2 = src[(size_t)s2 * 32 + lane];
        float4 v3 = src[(size_t)s3 * 32 + lane];
        acc.x += n0 * v0.x; acc.y += n0 * v0.y; acc.z += n0 * v0.z; acc.w += n0 * v0.w;
        acc.x += n1 * v1.x; acc.y += n1 * v1.y; acc.z += n1 * v1.z; acc.w += n1 * v1.w;
        acc.x += n2 * v2.x; acc.y += n2 * v2.y; acc.z += n2 * v2.z; acc.w += n2 * v2.w;
        acc.x += n3 * v3.x; acc.y += n3 * v3.y; acc.z += n3 * v3.z; acc.w += n3 * v3.w;
    }
    for (; k < end; k++) {
        int s = col[k];
        float n = nrm[k];
        float4 v = src[(size_t)s * 32 + lane];
        acc.x += n * v.x; acc.y += n * v.y; acc.z += n * v.z; acc.w += n * v.w;
    }
    dst[(size_t)d * 32 + lane] = acc;
}

// ---------------- scoring path ----------------

__global__ void acc_init_kernel(const float4* __restrict__ user_feat,
                                const float4* __restrict__ item_feat,
                                const int* __restrict__ ui,
                                const int* __restrict__ ii,
                                float* __restrict__ loss_out,
                                int has_loss) {
    int t = blockIdx.x * blockDim.x + threadIdx.x;  // over B*D/4
    const int per_row = D_N / 4;
    if (t >= B_N * per_row) return;
    int b = t / per_row;
    int d = t - b * per_row;
    ((float4*)g_acc_u)[t] = user_feat[(size_t)ui[b] * per_row + d];
    ((float4*)g_acc_i)[t] = item_feat[(size_t)ii[b] * per_row + d];
    if (t == 0 && has_loss) *loss_out = 0.0f;
}

__global__ void acc_gather_kernel(const float4* __restrict__ hu_new,
                                  const float4* __restrict__ hi_new,
                                  const int* __restrict__ ui,
                                  const int* __restrict__ ii,
                                  float coef) {
    int t = blockIdx.x * blockDim.x + threadIdx.x;
    const int per_row = D_N / 4;
    if (t >= B_N * per_row) return;
    int b = t / per_row;
    int d = t - b * per_row;

    float4 a = ((float4*)g_acc_u)[t];
    float4 h = hu_new[(size_t)ui[b] * per_row + d];
    a.x += coef * h.x; a.y += coef * h.y; a.z += coef * h.z; a.w += coef * h.w;
    ((float4*)g_acc_u)[t] = a;

    float4 ai = ((float4*)g_acc_i)[t];
    float4 hv = hi_new[(size_t)ii[b] * per_row + d];
    ai.x += coef * hv.x; ai.y += coef * hv.y; ai.z += coef * hv.z; ai.w += coef * hv.w;
    ((float4*)g_acc_i)[t] = ai;
}

__global__ void score_kernel(const float* __restrict__ labels,
                             float* __restrict__ pred_out,
                             float* __restrict__ loss_out,
                             int has_loss) {
    int warp = (blockIdx.x * blockDim.x + threadIdx.x) >> 5;
    int lane = threadIdx.x & 31;
    if (warp >= B_N) return;

    const float4* au = (const float4*)(g_acc_u + (size_t)warp * D_N);
    const float4* ai = (const float4*)(g_acc_i + (size_t)warp * D_N);
    float4 a = au[lane];
    float4 b = ai[lane];
    float s = a.x * b.x + a.y * b.y + a.z * b.z + a.w * b.w;
    #pragma unroll
    for (int off = 16; off > 0; off >>= 1)
        s += __shfl_down_sync(0xFFFFFFFFu, s, off);

    if (lane == 0) {
        float z = 1.0f / (1.0f + expf(-s));   // sigmoid(score)
        pred_out[warp] = z;
        if (has_loss) {
            float lbl = labels[warp];
            float term = fmaxf(z, 0.0f) - z * lbl + log1pf(expf(-fabsf(z)));
            atomicAdd(loss_out, term * (1.0f / (float)B_N));
        }
    }
}

// ---------------- host launch ----------------
extern "C" void kernel_launch(void* const* d_in, const int* in_sizes, int n_in,
                              void* d_out, int out_size) {
    const float* user_feat = (const float*)d_in[0];
    const float* item_feat = (const float*)d_in[1];
    const int*   u_idx     = (const int*)d_in[2];
    const int*   i_idx     = (const int*)d_in[3];
    const int*   ui        = (const int*)d_in[4];
    const int*   ii        = (const int*)d_in[5];
    const float* labels    = (const float*)d_in[6];

    float* out = (float*)d_out;
    int has_loss = (out_size > B_N) ? 1 : 0;
    float* pred_out = out + (out_size - B_N);
    float* loss_out = out;

    float* hu_base; float* hi_base;
    cudaGetSymbolAddress((void**)&hu_base, g_hu);
    cudaGetSymbolAddress((void**)&hi_base, g_hi);
    float* hu[2] = { hu_base, hu_base + (size_t)U_N * D_N };
    float* hi[2] = { hi_base, hi_base + (size_t)I_N * D_N };

    const int T = 256;
    const int acc_blocks = (B_N * (D_N / 4) + T - 1) / T;

    // 1) CSR build (degrees, scan, fill with inline norm)
    zero_deg_kernel<<<(U_N + T - 1) / T, T>>>();
    degree_kernel<<<(E_N + T - 1) / T, T>>>(u_idx, i_idx);
    scan2_kernel<<<2, 1024>>>();
    cursor_init_kernel<<<(U_N + T - 1) / T, T>>>();
    fill_kernel<<<(E_N + T - 1) / T, T>>>(u_idx, i_idx);

    // 2) scoring accumulators (layer-0 term, coefficient 1)
    acc_init_kernel<<<acc_blocks, T>>>((const float4*)user_feat,
                                       (const float4*)item_feat,
                                       ui, ii, loss_out, has_loss);

    // 3) three propagation layers, pure gather, self-loop fused
    const int gather_warps = U_N + I_N;
    const int gather_blocks = (gather_warps * 32 + T - 1) / T;
    const float coefs[3] = { 1.0f / 2.0f, 1.0f / 3.0f, 1.0f / 4.0f };

    const float4* su = (const float4*)user_feat;
    const float4* si = (const float4*)item_feat;
    for (int l = 0; l < 3; l++) {
        float4* du = (float4*)hu[l & 1];
        float4* di = (float4*)hi[l & 1];
        gather_kernel<<<gather_blocks, T>>>(su, si, du, di);
        acc_gather_kernel<<<acc_blocks, T>>>(du, di, ui, ii, coefs[l]);
        su = du; si = di;
    }

    // 4) scoring + loss
    score_kernel<<<(B_N * 32 + T - 1) / T, T>>>(labels, pred_out, loss_out, has_loss);
}

// round 3
// speedup vs baseline: 3.7927x; 1.4504x over previous
#include <cuda_runtime.h>
#include <cuda_fp16.h>
#include <math.h>

#define U_N 100000
#define I_N 50000
#define E_N 2000000
#define D_N 128
#define B_N 4096

#define CHUNK 1024
#define NCH_U ((U_N + CHUNK - 1) / CHUNK)   // 98
#define NCH_I ((I_N + CHUNK - 1) / CHUNK)   // 49

// ---------------- device scratch (static, allocation-free) ----------------
__device__ __half g_hu_h[2][(size_t)U_N * D_N];  // 2 x 25.6 MB
__device__ __half g_hi_h[2][(size_t)I_N * D_N];  // 2 x 12.8 MB
__device__ int    g_deg_u[U_N];
__device__ int    g_deg_i[I_N];
__device__ int    g_row_u[U_N + 1];
__device__ int    g_row_i[I_N + 1];
__device__ int    g_cur_u[U_N];
__device__ int    g_cur_i[I_N];
__device__ int    g_chunk_u[NCH_U];
__device__ int    g_chunk_i[NCH_I];
__device__ int2   g_adj_u[E_N];                  // {item, norm-bits} CSR by user
__device__ int2   g_adj_i[E_N];                  // {user, norm-bits} CSR by item
__device__ float  g_acc_u[(size_t)B_N * D_N];
__device__ float  g_acc_i[(size_t)B_N * D_N];

// ---------------- CSR construction ----------------

__global__ void zero_deg_kernel() {
    int t = blockIdx.x * blockDim.x + threadIdx.x;
    if (t < U_N) g_deg_u[t] = 0;
    if (t < I_N) g_deg_i[t] = 0;
}

__global__ void degree_kernel(const int* __restrict__ u_idx,
                              const int* __restrict__ i_idx) {
    int e = blockIdx.x * blockDim.x + threadIdx.x;
    if (e >= E_N) return;
    atomicAdd(&g_deg_u[u_idx[e]], 1);
    atomicAdd(&g_deg_i[i_idx[e]], 1);
}

// Phase A: per-chunk (1024 elems) partial sums. Blocks [0,NCH_U) -> U, rest -> I.
__global__ void scan_partial_kernel() {
    bool isU = blockIdx.x < NCH_U;
    const int* deg = isU ? g_deg_u : g_deg_i;
    int* part      = isU ? g_chunk_u : g_chunk_i;
    int  c         = isU ? blockIdx.x : blockIdx.x - NCH_U;
    int  n         = isU ? U_N : I_N;

    int base = c * CHUNK + threadIdx.x * 4;
    int s = 0;
    #pragma unroll
    for (int j = 0; j < 4; j++) {
        int idx = base + j;
        if (idx < n) s += deg[idx];
    }
    #pragma unroll
    for (int o = 16; o > 0; o >>= 1) s += __shfl_down_sync(0xFFFFFFFFu, s, o);
    __shared__ int ws[8];
    if ((threadIdx.x & 31) == 0) ws[threadIdx.x >> 5] = s;
    __syncthreads();
    if (threadIdx.x < 8) {
        int v = ws[threadIdx.x];
        #pragma unroll
        for (int o = 4; o > 0; o >>= 1) v += __shfl_down_sync(0xFFu, v, o);
        if (threadIdx.x == 0) part[c] = v;
    }
}

// Phase B: one block scans both partial arrays (exclusive).
__global__ void scan_chunkoff_kernel() {
    __shared__ int buf[128];
    int t = threadIdx.x;

    int v = (t < NCH_U) ? g_chunk_u[t] : 0;
    buf[t] = v; __syncthreads();
    #pragma unroll
    for (int o = 1; o < 128; o <<= 1) {
        int x = (t >= o) ? buf[t - o] : 0;
        __syncthreads(); buf[t] += x; __syncthreads();
    }
    if (t < NCH_U) g_chunk_u[t] = buf[t] - v;
    __syncthreads();

    int v2 = (t < NCH_I) ? g_chunk_i[t] : 0;
    buf[t] = v2; __syncthreads();
    #pragma unroll
    for (int o = 1; o < 128; o <<= 1) {
        int x = (t >= o) ? buf[t - o] : 0;
        __syncthreads(); buf[t] += x; __syncthreads();
    }
    if (t < NCH_I) g_chunk_i[t] = buf[t] - v2;
    if (t == 0) { g_row_u[U_N] = E_N; g_row_i[I_N] = E_N; }
}

// Phase C: per-chunk local exclusive scan + chunk base; also init cursors.
__global__ void scan_final_kernel() {
    bool isU = blockIdx.x < NCH_U;
    const int* deg = isU ? g_deg_u : g_deg_i;
    int* row       = isU ? g_row_u : g_row_i;
    int* cur       = isU ? g_cur_u : g_cur_i;
    int  c         = isU ? blockIdx.x : blockIdx.x - NCH_U;
    int  n         = isU ? U_N : I_N;
    int  cbase     = isU ? g_chunk_u[c] : g_chunk_i[c];

    int base = c * CHUNK + threadIdx.x * 4;
    int d[4], e[4];
    int s = 0;
    #pragma unroll
    for (int j = 0; j < 4; j++) {
        int idx = base + j;
        d[j] = (idx < n) ? deg[idx] : 0;
        e[j] = s;
        s += d[j];
    }
    int lane = threadIdx.x & 31, w = threadIdx.x >> 5;
    int inc = s;
    #pragma unroll
    for (int o = 1; o < 32; o <<= 1) {
        int x = __shfl_up_sync(0xFFFFFFFFu, inc, o);
        if (lane >= o) inc += x;
    }
    __shared__ int ws[8];
    if (lane == 31) ws[w] = inc;
    __syncthreads();
    if (threadIdx.x < 8) {
        int v = ws[threadIdx.x];
        #pragma unroll
        for (int o = 1; o < 8; o <<= 1) {
            int x = __shfl_up_sync(0xFFu, v, o);
            if ((int)threadIdx.x >= o) v += x;
        }
        ws[threadIdx.x] = v;
    }
    __syncthreads();
    int excl = inc - s + (w > 0 ? ws[w - 1] : 0) + cbase;
    #pragma unroll
    for (int j = 0; j < 4; j++) {
        int idx = base + j;
        if (idx < n) { int r = excl + e[j]; row[idx] = r; cur[idx] = r; }
    }
}

// Fill both CSR adjacency arrays, norm packed with the column index.
__global__ void fill_kernel(const int* __restrict__ u_idx,
                            const int* __restrict__ i_idx) {
    int e = blockIdx.x * blockDim.x + threadIdx.x;
    if (e >= E_N) return;
    int u = u_idx[e];
    int i = i_idx[e];
    float nf = rsqrtf((float)g_deg_u[u] * (float)g_deg_i[i]);
    int nb = __float_as_int(nf);
    int pu = atomicAdd(&g_cur_u[u], 1);
    g_adj_u[pu] = make_int2(i, nb);
    int pi = atomicAdd(&g_cur_i[i], 1);
    g_adj_i[pi] = make_int2(u, nb);
}

// ---------------- fp32 -> fp16 input conversion ----------------
__global__ void convert_kernel(const float4* __restrict__ user_feat,
                               const float4* __restrict__ item_feat,
                               uint2* __restrict__ hu0,
                               uint2* __restrict__ hi0) {
    int t = blockIdx.x * blockDim.x + threadIdx.x;
    const int nu = U_N * D_N / 4;
    const int ni = I_N * D_N / 4;
    float4 v; uint2* dst; int o;
    if (t < nu)            { v = user_feat[t]; dst = hu0; o = t; }
    else if (t < nu + ni)  { v = item_feat[t - nu]; dst = hi0; o = t - nu; }
    else return;
    __half2 h0 = __floats2half2_rn(v.x, v.y);
    __half2 h1 = __floats2half2_rn(v.z, v.w);
    uint2 out;
    out.x = *reinterpret_cast<unsigned*>(&h0);
    out.y = *reinterpret_cast<unsigned*>(&h1);
    dst[o] = out;
}

// ---------------- propagation: pure gather over fp16 rows ----------------
// One warp per destination row; lane owns 4 half dims (one uint2).
__global__ void gather_kernel(const uint2* __restrict__ src_u,
                              const uint2* __restrict__ src_i,
                              uint2* __restrict__ dst_u,
                              uint2* __restrict__ dst_i) {
    int w = (blockIdx.x * blockDim.x + threadIdx.x) >> 5;
    int lane = threadIdx.x & 31;

    const int* rp; const int2* adj;
    const uint2* src; const uint2* self; uint2* dst; int d;
    if (w < U_N) {
        d = w; rp = g_row_u; adj = g_adj_u;
        src = src_i; self = src_u; dst = dst_u;
    } else if (w < U_N + I_N) {
        d = w - U_N; rp = g_row_i; adj = g_adj_i;
        src = src_u; self = src_i; dst = dst_i;
    } else return;

    int start = rp[d];
    int end   = rp[d + 1];

    uint2 sv = self[(size_t)d * 32 + lane];
    float2 f0 = __half22float2(*reinterpret_cast<__half2*>(&sv.x));
    float2 f1 = __half22float2(*reinterpret_cast<__half2*>(&sv.y));
    float a0 = f0.x, a1 = f0.y, a2 = f1.x, a3 = f1.y;

    int k = start;
    for (; k + 4 <= end; k += 4) {
        int2 e0 = adj[k], e1 = adj[k + 1], e2 = adj[k + 2], e3 = adj[k + 3];
        uint2 v0 = src[(size_t)e0.x * 32 + lane];
        uint2 v1 = src[(size_t)e1.x * 32 + lane];
        uint2 v2 = src[(size_t)e2.x * 32 + lane];
        uint2 v3 = src[(size_t)e3.x * 32 + lane];
        float n0 = __int_as_float(e0.y), n1 = __int_as_float(e1.y);
        float n2 = __int_as_float(e2.y), n3 = __int_as_float(e3.y);
        float2 p, q;
        p = __half22float2(*reinterpret_cast<__half2*>(&v0.x));
        q = __half22float2(*reinterpret_cast<__half2*>(&v0.y));
        a0 += n0 * p.x; a1 += n0 * p.y; a2 += n0 * q.x; a3 += n0 * q.y;
        p = __half22float2(*reinterpret_cast<__half2*>(&v1.x));
        q = __half22float2(*reinterpret_cast<__half2*>(&v1.y));
        a0 += n1 * p.x; a1 += n1 * p.y; a2 += n1 * q.x; a3 += n1 * q.y;
        p = __half22float2(*reinterpret_cast<__half2*>(&v2.x));
        q = __half22float2(*reinterpret_cast<__half2*>(&v2.y));
        a0 += n2 * p.x; a1 += n2 * p.y; a2 += n2 * q.x; a3 += n2 * q.y;
        p = __half22float2(*reinterpret_cast<__half2*>(&v3.x));
        q = __half22float2(*reinterpret_cast<__half2*>(&v3.y));
        a0 += n3 * p.x; a1 += n3 * p.y; a2 += n3 * q.x; a3 += n3 * q.y;
    }
    for (; k < end; k++) {
        int2 e0 = adj[k];
        uint2 v0 = src[(size_t)e0.x * 32 + lane];
        float n0 = __int_as_float(e0.y);
        float2 p = __half22float2(*reinterpret_cast<__half2*>(&v0.x));
        float2 q = __half22float2(*reinterpret_cast<__half2*>(&v0.y));
        a0 += n0 * p.x; a1 += n0 * p.y; a2 += n0 * q.x; a3 += n0 * q.y;
    }

    __half2 h0 = __floats2half2_rn(a0, a1);
    __half2 h1 = __floats2half2_rn(a2, a3);
    uint2 out;
    out.x = *reinterpret_cast<unsigned*>(&h0);
    out.y = *reinterpret_cast<unsigned*>(&h1);
    dst[(size_t)d * 32 + lane] = out;
}

// ---------------- scoring path ----------------

__global__ void acc_init_kernel(const float4* __restrict__ user_feat,
                                const float4* __restrict__ item_feat,
                                const int* __restrict__ ui,
                                const int* __restrict__ ii,
                                float* __restrict__ loss_out,
                                int has_loss) {
    int t = blockIdx.x * blockDim.x + threadIdx.x;  // over B*32
    const int per_row = D_N / 4;
    if (t >= B_N * per_row) return;
    int b = t / per_row;
    int d = t - b * per_row;
    ((float4*)g_acc_u)[t] = user_feat[(size_t)ui[b] * per_row + d];
    ((float4*)g_acc_i)[t] = item_feat[(size_t)ii[b] * per_row + d];
    if (t == 0 && has_loss) *loss_out = 0.0f;
}

// acc += coef * (half rows just produced)
__global__ void acc_gather_kernel(const uint2* __restrict__ hu_new,
                                  const uint2* __restrict__ hi_new,
                                  const int* __restrict__ ui,
                                  const int* __restrict__ ii,
                                  float coef) {
    int t = blockIdx.x * blockDim.x + threadIdx.x;
    const int per_row = D_N / 4;
    if (t >= B_N * per_row) return;
    int b = t / per_row;
    int d = t - b * per_row;

    uint2 hv = hu_new[(size_t)ui[b] * per_row + d];
    float2 p = __half22float2(*reinterpret_cast<__half2*>(&hv.x));
    float2 q = __half22float2(*reinterpret_cast<__half2*>(&hv.y));
    float4 a = ((float4*)g_acc_u)[t];
    a.x += coef * p.x; a.y += coef * p.y; a.z += coef * q.x; a.w += coef * q.y;
    ((float4*)g_acc_u)[t] = a;

    uint2 hv2 = hi_new[(size_t)ii[b] * per_row + d];
    p = __half22float2(*reinterpret_cast<__half2*>(&hv2.x));
    q = __half22float2(*reinterpret_cast<__half2*>(&hv2.y));
    float4 ai = ((float4*)g_acc_i)[t];
    ai.x += coef * p.x; ai.y += coef * p.y; ai.z += coef * q.x; ai.w += coef * q.y;
    ((float4*)g_acc_i)[t] = ai;
}

__global__ void score_kernel(const float* __restrict__ labels,
                             float* __restrict__ pred_out,
                             float* __restrict__ loss_out,
                             int has_loss) {
    int warp = (blockIdx.x * blockDim.x + threadIdx.x) >> 5;
    int lane = threadIdx.x & 31;
    if (warp >= B_N) return;

    const float4* au = (const float4*)(g_acc_u + (size_t)warp * D_N);
    const float4* ai = (const float4*)(g_acc_i + (size_t)warp * D_N);
    float4 a = au[lane];
    float4 b = ai[lane];
    float s = a.x * b.x + a.y * b.y + a.z * b.z + a.w * b.w;
    #pragma unroll
    for (int off = 16; off > 0; off >>= 1)
        s += __shfl_down_sync(0xFFFFFFFFu, s, off);

    if (lane == 0) {
        float z = 1.0f / (1.0f + expf(-s));
        pred_out[warp] = z;
        if (has_loss) {
            float lbl = labels[warp];
            float term = fmaxf(z, 0.0f) - z * lbl + log1pf(expf(-fabsf(z)));
            atomicAdd(loss_out, term * (1.0f / (float)B_N));
        }
    }
}

// ---------------- host launch ----------------
extern "C" void kernel_launch(void* const* d_in, const int* in_sizes, int n_in,
                              void* d_out, int out_size) {
    const float* user_feat = (const float*)d_in[0];
    const float* item_feat = (const float*)d_in[1];
    const int*   u_idx     = (const int*)d_in[2];
    const int*   i_idx     = (const int*)d_in[3];
    const int*   ui        = (const int*)d_in[4];
    const int*   ii        = (const int*)d_in[5];
    const float* labels    = (const float*)d_in[6];

    float* out = (float*)d_out;
    int has_loss = (out_size > B_N) ? 1 : 0;
    float* pred_out = out + (out_size - B_N);
    float* loss_out = out;

    __half* hu_base; __half* hi_base;
    cudaGetSymbolAddress((void**)&hu_base, g_hu_h);
    cudaGetSymbolAddress((void**)&hi_base, g_hi_h);
    __half* hu[2] = { hu_base, hu_base + (size_t)U_N * D_N };
    __half* hi[2] = { hi_base, hi_base + (size_t)I_N * D_N };

    const int T = 256;
    const int acc_blocks = (B_N * (D_N / 4) + T - 1) / T;
    const int conv_blocks = ((U_N + I_N) * (D_N / 4) + T - 1) / T;

    // 1) CSR build
    zero_deg_kernel<<<(U_N + T - 1) / T, T>>>();
    degree_kernel<<<(E_N + T - 1) / T, T>>>(u_idx, i_idx);
    scan_partial_kernel<<<NCH_U + NCH_I, 256>>>();
    scan_chunkoff_kernel<<<1, 128>>>();
    scan_final_kernel<<<NCH_U + NCH_I, 256>>>();
    fill_kernel<<<(E_N + T - 1) / T, T>>>(u_idx, i_idx);

    // 2) fp16 source buffers + scoring accumulators (layer-0 term)
    convert_kernel<<<conv_blocks, T>>>((const float4*)user_feat,
                                       (const float4*)item_feat,
                                       (uint2*)hu[0], (uint2*)hi[0]);
    acc_init_kernel<<<acc_blocks, T>>>((const float4*)user_feat,
                                       (const float4*)item_feat,
                                       ui, ii, loss_out, has_loss);

    // 3) three propagation layers (ping-pong half buffers)
    const int gather_blocks = ((U_N + I_N) * 32 + T - 1) / T;
    const float coefs[3] = { 1.0f / 2.0f, 1.0f / 3.0f, 1.0f / 4.0f };
    int cur = 0;
    for (int l = 0; l < 3; l++) {
        int nxt = 1 - cur;
        gather_kernel<<<gather_blocks, T>>>((const uint2*)hu[cur],
                                            (const uint2*)hi[cur],
                                            (uint2*)hu[nxt], (uint2*)hi[nxt]);
        acc_gather_kernel<<<acc_blocks, T>>>((const uint2*)hu[nxt],
                                             (const uint2*)hi[nxt],
                                             ui, ii, coefs[l]);
        cur = nxt;
    }

    // 4) scoring + loss
    score_kernel<<<(B_N * 32 + T - 1) / T, T>>>(labels, pred_out, loss_out, has_loss);
}